// round 2
// baseline (speedup 1.0000x reference)
#include <cuda_runtime.h>
#include <math.h>

#define Bn   65536
#define Tn   5
#define OBSn 128
#define ACTn 32
#define Hn   64
#define BT   (Bn*Tn)
#define EPSf 1e-12f

// ---------------- scratch (device globals; no allocation allowed) ----------------
__device__ float g_x[BT * Hn];          // MLP output, [B*T, 64]
__device__ float g_h[2][Bn * Hn];       // LSTM hidden state per direction
__device__ float g_c[2][Bn * Hn];       // LSTM cell state per direction
__device__ float g_ys[2][BT * Hn];      // LSTM outputs per direction (bw in reversed-time order)

extern __shared__ float smem[];

__device__ __forceinline__ float sigf(float x) { return 1.f / (1.f + expf(-x)); }

// =====================================================================================
// Kernel 1: fused MLP.  Block = 64 rows of [B*T], 256 threads.
//   x = relu(LN(relu(LN(LN(ud) @ W1 + b1)) ++ action @ W2 + b2))   (LNs per row)
// =====================================================================================
__global__ __launch_bounds__(256)
void mlp_kernel(const float* __restrict__ ud, const float* __restrict__ act,
                const float* __restrict__ ln0g, const float* __restrict__ ln0b,
                const float* __restrict__ W1, const float* __restrict__ b1,
                const float* __restrict__ ln1g, const float* __restrict__ ln1b,
                const float* __restrict__ W2, const float* __restrict__ b2,
                const float* __restrict__ ln2g, const float* __restrict__ ln2b)
{
    float* sW1 = smem;                 // 128*64 = 8192
    float* sW2 = sW1 + 128 * 64;       // 96*64  = 6144
    float* sX  = sW2 + 96 * 64;        // 64 rows * 132 (pad)  = 8448
    float* sX2 = sX + 64 * 132;        // 64 rows * 100 (pad)  = 6400
    float* sP  = sX2 + 64 * 100;       // params: 640 floats
    // sP: [0:128) ln0g, [128:256) ln0b, [256:320) b1, [320:384) ln1g,
    //     [384:448) ln1b, [448:512) b2, [512:576) ln2g, [576:640) ln2b

    const int tid = threadIdx.x;
    for (int i = tid; i < 128 * 64; i += 256) sW1[i] = W1[i];
    for (int i = tid; i < 96 * 64;  i += 256) sW2[i] = W2[i];
    if (tid < 128) { sP[tid] = ln0g[tid]; sP[128 + tid] = ln0b[tid]; }
    if (tid < 64) {
        sP[256 + tid] = b1[tid];  sP[320 + tid] = ln1g[tid]; sP[384 + tid] = ln1b[tid];
        sP[448 + tid] = b2[tid];  sP[512 + tid] = ln2g[tid]; sP[576 + tid] = ln2b[tid];
    }

    const int r0 = blockIdx.x * 64;

    // load ud tile (64 x 128) into sX, coalesced float4
    #pragma unroll
    for (int j = 0; j < 8; j++) {
        int f = tid + j * 256;              // 2048 float4s
        int row = f >> 5, c4 = f & 31;
        float4 v = reinterpret_cast<const float4*>(ud + (size_t)(r0 + row) * 128)[c4];
        *reinterpret_cast<float4*>(&sX[row * 132 + c4 * 4]) = v;
    }
    // load action tile (64 x 32) into sX2 cols [64,96)
    #pragma unroll
    for (int j = 0; j < 2; j++) {
        int f = tid + j * 256;              // 512 float4s
        int row = f >> 3, c4 = f & 7;
        float4 v = reinterpret_cast<const float4*>(act + (size_t)(r0 + row) * 32)[c4];
        *reinterpret_cast<float4*>(&sX2[row * 100 + 64 + c4 * 4]) = v;
    }
    __syncthreads();

    const int w = tid >> 5, lane = tid & 31;

    // LN0 over 128 features (warp per row, 8 rows/warp)
    for (int rr = 0; rr < 8; rr++) {
        int row = w * 8 + rr;
        float v0 = sX[row * 132 + lane];
        float v1 = sX[row * 132 + lane + 32];
        float v2 = sX[row * 132 + lane + 64];
        float v3 = sX[row * 132 + lane + 96];
        float s = v0 + v1 + v2 + v3;
        float q = v0 * v0 + v1 * v1 + v2 * v2 + v3 * v3;
        #pragma unroll
        for (int o = 16; o; o >>= 1) { s += __shfl_xor_sync(~0u, s, o); q += __shfl_xor_sync(~0u, q, o); }
        float m = s * (1.f / 128.f);
        float var = q * (1.f / 128.f) - m * m;
        float rs = rsqrtf(var + EPSf);
        sX[row * 132 + lane]      = (v0 - m) * rs * sP[lane]      + sP[128 + lane];
        sX[row * 132 + lane + 32] = (v1 - m) * rs * sP[lane + 32] + sP[128 + lane + 32];
        sX[row * 132 + lane + 64] = (v2 - m) * rs * sP[lane + 64] + sP[128 + lane + 64];
        sX[row * 132 + lane + 96] = (v3 - m) * rs * sP[lane + 96] + sP[128 + lane + 96];
    }
    __syncthreads();

    const int ty = tid >> 4, tx = tid & 15;
    const int ry = ty * 4, cx = tx * 4;

    // GEMM1: (64x128)@(128x64), 4x4 micro-tile per thread
    float acc[4][4];
    #pragma unroll
    for (int i = 0; i < 4; i++)
        #pragma unroll
        for (int j = 0; j < 4; j++) acc[i][j] = 0.f;

    #pragma unroll 4
    for (int k = 0; k < 128; k++) {
        float4 wv = *reinterpret_cast<const float4*>(&sW1[k * 64 + cx]);
        float av[4];
        #pragma unroll
        for (int i = 0; i < 4; i++) av[i] = sX[(ry + i) * 132 + k];
        #pragma unroll
        for (int i = 0; i < 4; i++) {
            acc[i][0] += av[i] * wv.x; acc[i][1] += av[i] * wv.y;
            acc[i][2] += av[i] * wv.z; acc[i][3] += av[i] * wv.w;
        }
    }
    __syncthreads();   // all sX reads done before overwrite

    // y1 = acc + b1 -> sX (reuse, stride 132)
    #pragma unroll
    for (int i = 0; i < 4; i++) {
        float4 o;
        o.x = acc[i][0] + sP[256 + cx + 0];
        o.y = acc[i][1] + sP[256 + cx + 1];
        o.z = acc[i][2] + sP[256 + cx + 2];
        o.w = acc[i][3] + sP[256 + cx + 3];
        *reinterpret_cast<float4*>(&sX[(ry + i) * 132 + cx]) = o;
    }
    __syncthreads();

    // LN1 + relu -> sX2 cols [0,64)
    for (int rr = 0; rr < 8; rr++) {
        int row = w * 8 + rr;
        float v0 = sX[row * 132 + lane];
        float v1 = sX[row * 132 + lane + 32];
        float s = v0 + v1, q = v0 * v0 + v1 * v1;
        #pragma unroll
        for (int o = 16; o; o >>= 1) { s += __shfl_xor_sync(~0u, s, o); q += __shfl_xor_sync(~0u, q, o); }
        float m = s * (1.f / 64.f);
        float var = q * (1.f / 64.f) - m * m;
        float rs = rsqrtf(var + EPSf);
        float y0 = (v0 - m) * rs * sP[320 + lane]      + sP[384 + lane];
        float y1 = (v1 - m) * rs * sP[320 + lane + 32] + sP[384 + lane + 32];
        sX2[row * 100 + lane]      = fmaxf(y0, 0.f);
        sX2[row * 100 + lane + 32] = fmaxf(y1, 0.f);
    }
    __syncthreads();

    // GEMM2: (64x96)@(96x64)
    float acc2[4][4];
    #pragma unroll
    for (int i = 0; i < 4; i++)
        #pragma unroll
        for (int j = 0; j < 4; j++) acc2[i][j] = 0.f;

    #pragma unroll 4
    for (int k = 0; k < 96; k++) {
        float4 wv = *reinterpret_cast<const float4*>(&sW2[k * 64 + cx]);
        float av[4];
        #pragma unroll
        for (int i = 0; i < 4; i++) av[i] = sX2[(ry + i) * 100 + k];
        #pragma unroll
        for (int i = 0; i < 4; i++) {
            acc2[i][0] += av[i] * wv.x; acc2[i][1] += av[i] * wv.y;
            acc2[i][2] += av[i] * wv.z; acc2[i][3] += av[i] * wv.w;
        }
    }
    __syncthreads();

    // y2 = acc2 + b2 -> sX
    #pragma unroll
    for (int i = 0; i < 4; i++) {
        float4 o;
        o.x = acc2[i][0] + sP[448 + cx + 0];
        o.y = acc2[i][1] + sP[448 + cx + 1];
        o.z = acc2[i][2] + sP[448 + cx + 2];
        o.w = acc2[i][3] + sP[448 + cx + 3];
        *reinterpret_cast<float4*>(&sX[(ry + i) * 132 + cx]) = o;
    }
    __syncthreads();

    // LN2 + relu -> global g_x
    for (int rr = 0; rr < 8; rr++) {
        int row = w * 8 + rr;
        float v0 = sX[row * 132 + lane];
        float v1 = sX[row * 132 + lane + 32];
        float s = v0 + v1, q = v0 * v0 + v1 * v1;
        #pragma unroll
        for (int o = 16; o; o >>= 1) { s += __shfl_xor_sync(~0u, s, o); q += __shfl_xor_sync(~0u, q, o); }
        float m = s * (1.f / 64.f);
        float var = q * (1.f / 64.f) - m * m;
        float rs = rsqrtf(var + EPSf);
        float y0 = (v0 - m) * rs * sP[512 + lane]      + sP[576 + lane];
        float y1 = (v1 - m) * rs * sP[512 + lane + 32] + sP[576 + lane + 32];
        size_t base = (size_t)(r0 + row) * 64;
        g_x[base + lane]      = fmaxf(y0, 0.f);
        g_x[base + lane + 32] = fmaxf(y1, 0.f);
    }
}

// =====================================================================================
// Kernel 2: one LSTM time step, both directions (blockIdx.y).
// Block = 64 batch rows, 256 threads. gates = [x_sel, h] @ K + b, fused gate epilogue.
// Thread owns 4 rows x (4 gates x 4 hidden) -> register-resident epilogue.
// =====================================================================================
__global__ __launch_bounds__(256, 2)
void lstm_step_kernel(const float* __restrict__ fw_k, const float* __restrict__ fw_b,
                      const float* __restrict__ bw_k, const float* __restrict__ bw_b,
                      const int* __restrict__ au, int t, int first)
{
    float* sK  = smem;                  // 64*256 = 16384
    float* sA  = sK + 64 * 256;         // 64*68  = 4352
    float* sB  = sA + 64 * 68;          // 256
    int*   sTs = (int*)(sB + 256);      // 64 (source time per row)
    int*   sAu = sTs + 64;              // 64

    const int dir = blockIdx.y;
    const float* K    = dir ? bw_k : fw_k;
    const float* bias = dir ? bw_b : fw_b;
    float* gh = g_h[dir];
    float* gc = g_c[dir];
    float* gy = g_ys[dir];

    const int b0 = blockIdx.x * 64;
    const int tid = threadIdx.x;

    sB[tid] = bias[tid];
    if (tid < 64) {
        int b = b0 + tid;
        int a = au[b];
        sAu[tid] = a;
        sTs[tid] = dir ? ((t < a) ? (a - 1 - t) : t) : t;
    }
    __syncthreads();

    const int ty = tid >> 4, tx = tid & 15;
    const int ry = ty * 4, hx = tx * 4;

    float acc[4][4][4];   // [row][gate][hidden]
    #pragma unroll
    for (int i = 0; i < 4; i++)
        #pragma unroll
        for (int g = 0; g < 4; g++)
            #pragma unroll
            for (int j = 0; j < 4; j++) acc[i][g][j] = 0.f;

    const int nkc = first ? 1 : 2;   // h==0 on step 0: skip recurrent half
    for (int kc = 0; kc < nkc; kc++) {
        // --- load A chunk (64 rows x 64 cols) ---
        {
            int r = tid >> 2, q = tid & 3;
            int b = b0 + r;
            float4 v0, v1, v2, v3;
            if (kc == 0) {
                const float4* src = reinterpret_cast<const float4*>(g_x + ((size_t)b * 5 + sTs[r]) * 64);
                v0 = src[q * 4 + 0]; v1 = src[q * 4 + 1]; v2 = src[q * 4 + 2]; v3 = src[q * 4 + 3];
            } else {
                const float4* src = reinterpret_cast<const float4*>(gh + (size_t)b * 64);
                v0 = src[q * 4 + 0]; v1 = src[q * 4 + 1]; v2 = src[q * 4 + 2]; v3 = src[q * 4 + 3];
            }
            float4* dst = reinterpret_cast<float4*>(&sA[r * 68 + q * 16]);
            dst[0] = v0; dst[1] = v1; dst[2] = v2; dst[3] = v3;
        }
        // --- load K chunk (64 x 256) ---
        #pragma unroll
        for (int j = 0; j < 16; j++) {
            int f = tid + j * 256;          // 4096 float4s
            int kk = f >> 6, c4 = f & 63;
            reinterpret_cast<float4*>(&sK[kk * 256 + c4 * 4])[0] =
                reinterpret_cast<const float4*>(K + (size_t)(kc * 64 + kk) * 256)[c4];
        }
        __syncthreads();

        #pragma unroll 2
        for (int kk = 0; kk < 64; kk++) {
            float av[4];
            #pragma unroll
            for (int i = 0; i < 4; i++) av[i] = sA[(ry + i) * 68 + kk];
            #pragma unroll
            for (int g = 0; g < 4; g++) {
                float4 wv = *reinterpret_cast<const float4*>(&sK[kk * 256 + g * 64 + hx]);
                #pragma unroll
                for (int i = 0; i < 4; i++) {
                    acc[i][g][0] += av[i] * wv.x;
                    acc[i][g][1] += av[i] * wv.y;
                    acc[i][g][2] += av[i] * wv.z;
                    acc[i][g][3] += av[i] * wv.w;
                }
            }
        }
        __syncthreads();
    }

    // --- gate epilogue (register resident) ---
    float bi[4], bj[4], bf[4], bo[4];
    #pragma unroll
    for (int j = 0; j < 4; j++) {
        bi[j] = sB[0   + hx + j];
        bj[j] = sB[64  + hx + j];
        bf[j] = sB[128 + hx + j];
        bo[j] = sB[192 + hx + j];
    }
    #pragma unroll
    for (int i = 0; i < 4; i++) {
        int b = b0 + ry + i;
        int a = sAu[ry + i];
        bool valid = (t < a);
        size_t hbase = (size_t)b * 64 + hx;
        float4 cprev = make_float4(0.f, 0.f, 0.f, 0.f);
        float4 hprev = make_float4(0.f, 0.f, 0.f, 0.f);
        if (!first) {
            cprev = *reinterpret_cast<const float4*>(gc + hbase);
            hprev = *reinterpret_cast<const float4*>(gh + hbase);
        }
        float4 cn, hn, yn;
        float* cp = &cprev.x; float* hp = &hprev.x;
        float* cw = &cn.x;    float* hw = &hn.x;    float* yw = &yn.x;
        #pragma unroll
        for (int j = 0; j < 4; j++) {
            float gi = acc[i][0][j] + bi[j];
            float gj = acc[i][1][j] + bj[j];
            float gf = acc[i][2][j] + bf[j];
            float go = acc[i][3][j] + bo[j];
            float c_ = sigf(gf + 1.f) * cp[j] + sigf(gi) * tanhf(gj);
            float h_ = sigf(go) * tanhf(c_);
            cw[j] = valid ? c_ : cp[j];
            hw[j] = valid ? h_ : hp[j];
            yw[j] = valid ? h_ : 0.f;
        }
        *reinterpret_cast<float4*>(gc + hbase) = cn;
        *reinterpret_cast<float4*>(gh + hbase) = hn;
        *reinterpret_cast<float4*>(gy + ((size_t)b * 5 + t) * 64 + hx) = yn;
    }
}

// =====================================================================================
// Kernel 3: LN over (T,2H) per batch + relu + conv dot + masked sum.  Warp per batch.
// =====================================================================================
__global__ __launch_bounds__(256)
void final_kernel(const float* __restrict__ mask,
                  const float* __restrict__ ln3g, const float* __restrict__ ln3b,
                  const float* __restrict__ convw, const float* __restrict__ convb,
                  const int* __restrict__ au, float* __restrict__ out)
{
    int b = blockIdx.x * 8 + (threadIdx.x >> 5);
    int lane = threadIdx.x & 31;
    int a = au[b];

    float vals[20];   // [t][4]: fw(lane), fw(lane+32), bw(lane), bw(lane+32)
    float s = 0.f, q = 0.f;
    #pragma unroll
    for (int t = 0; t < 5; t++) {
        int rt = (t < a) ? (a - 1 - t) : t;
        size_t fbase = ((size_t)b * 5 + t)  * 64;
        size_t bbase = ((size_t)b * 5 + rt) * 64;
        float v0 = g_ys[0][fbase + lane];
        float v1 = g_ys[0][fbase + lane + 32];
        float v2 = g_ys[1][bbase + lane];
        float v3 = g_ys[1][bbase + lane + 32];
        vals[t * 4 + 0] = v0; vals[t * 4 + 1] = v1;
        vals[t * 4 + 2] = v2; vals[t * 4 + 3] = v3;
        s += v0 + v1 + v2 + v3;
        q += v0 * v0 + v1 * v1 + v2 * v2 + v3 * v3;
    }
    #pragma unroll
    for (int o = 16; o; o >>= 1) { s += __shfl_xor_sync(~0u, s, o); q += __shfl_xor_sync(~0u, q, o); }
    float m = s * (1.f / 640.f);
    float var = q * (1.f / 640.f) - m * m;
    float rs = rsqrtf(var + EPSf);

    // channels: fw -> [lane, lane+32], bw -> [64+lane, 96+lane]
    float g0 = ln3g[lane],      c0 = ln3b[lane],      w0 = convw[lane];
    float g1 = ln3g[lane + 32], c1 = ln3b[lane + 32], w1 = convw[lane + 32];
    float g2 = ln3g[lane + 64], c2 = ln3b[lane + 64], w2 = convw[lane + 64];
    float g3 = ln3g[lane + 96], c3 = ln3b[lane + 96], w3 = convw[lane + 96];

    float accq = 0.f, msum = 0.f;
    #pragma unroll
    for (int t = 0; t < 5; t++) {
        float p =
            fmaxf((vals[t*4+0] - m) * rs * g0 + c0, 0.f) * w0 +
            fmaxf((vals[t*4+1] - m) * rs * g1 + c1, 0.f) * w1 +
            fmaxf((vals[t*4+2] - m) * rs * g2 + c2, 0.f) * w2 +
            fmaxf((vals[t*4+3] - m) * rs * g3 + c3, 0.f) * w3;
        float mk = mask[(size_t)b * 5 + t];
        accq += p * mk;
        msum += mk;
    }
    #pragma unroll
    for (int o = 16; o; o >>= 1) accq += __shfl_xor_sync(~0u, accq, o);
    if (lane == 0) out[b] = accq + convb[0] * msum;
}

// =====================================================================================
extern "C" void kernel_launch(void* const* d_in, const int* in_sizes, int n_in,
                              void* d_out, int out_size)
{
    (void)in_sizes; (void)n_in; (void)out_size;
    const float* ud     = (const float*)d_in[0];
    const float* action = (const float*)d_in[1];
    const float* mask   = (const float*)d_in[2];
    const float* ln0g   = (const float*)d_in[3];
    const float* ln0b   = (const float*)d_in[4];
    const float* W1     = (const float*)d_in[5];
    const float* b1     = (const float*)d_in[6];
    const float* ln1g   = (const float*)d_in[7];
    const float* ln1b   = (const float*)d_in[8];
    const float* W2     = (const float*)d_in[9];
    const float* b2     = (const float*)d_in[10];
    const float* ln2g   = (const float*)d_in[11];
    const float* ln2b   = (const float*)d_in[12];
    const float* fw_k   = (const float*)d_in[13];
    const float* fw_b   = (const float*)d_in[14];
    const float* bw_k   = (const float*)d_in[15];
    const float* bw_b   = (const float*)d_in[16];
    const float* ln3g   = (const float*)d_in[17];
    const float* ln3b   = (const float*)d_in[18];
    const float* convw  = (const float*)d_in[19];
    const float* convb  = (const float*)d_in[20];
    const int*   au     = (const int*)d_in[21];

    const int MLP_SMEM  = (128*64 + 96*64 + 64*132 + 64*100 + 640) * 4;   // 119296 B
    const int LSTM_SMEM = (64*256 + 64*68 + 256 + 64 + 64) * 4;          // 84480 B

    cudaFuncSetAttribute(mlp_kernel,      cudaFuncAttributeMaxDynamicSharedMemorySize, MLP_SMEM);
    cudaFuncSetAttribute(lstm_step_kernel, cudaFuncAttributeMaxDynamicSharedMemorySize, LSTM_SMEM);

    mlp_kernel<<<BT / 64, 256, MLP_SMEM>>>(ud, action, ln0g, ln0b, W1, b1,
                                           ln1g, ln1b, W2, b2, ln2g, ln2b);

    for (int t = 0; t < Tn; t++) {
        lstm_step_kernel<<<dim3(Bn / 64, 2), 256, LSTM_SMEM>>>(
            fw_k, fw_b, bw_k, bw_b, au, t, (t == 0) ? 1 : 0);
    }

    final_kernel<<<Bn / 8, 256>>>(mask, ln3g, ln3b, convw, convb, au, (float*)d_out);
}

// round 3
// speedup vs baseline: 1.1417x; 1.1417x over previous
#include <cuda_runtime.h>
#include <math.h>

#define Bn   65536
#define Tn   5
#define OBSn 128
#define ACTn 32
#define Hn   64
#define BT   (Bn*Tn)
#define EPSf 1e-12f

typedef unsigned long long u64;

// ---------------- scratch (device globals; no allocation allowed) ----------------
__device__ float g_x[BT * Hn];          // MLP output, [B*T, 64]
__device__ float g_h[2][Bn * Hn];       // LSTM hidden state per direction
__device__ float g_c[2][Bn * Hn];       // LSTM cell state per direction
__device__ float g_ys[2][BT * Hn];      // LSTM outputs per direction (bw in reversed-time order)

extern __shared__ float smem[];

__device__ __forceinline__ float sigf(float x) { return 1.f / (1.f + expf(-x)); }

// ---------------- packed f32x2 helpers (FFMA2 — ptxas never emits this itself) ----
__device__ __forceinline__ u64 splat2(float x) {
    u64 r; asm("mov.b64 %0, {%1, %1};" : "=l"(r) : "f"(x)); return r;
}
__device__ __forceinline__ void ffma2(u64& d, u64 a, u64 b) {
    asm("fma.rn.f32x2 %0, %1, %2, %0;" : "+l"(d) : "l"(a), "l"(b));
}
__device__ __forceinline__ void lds_v2u64(u64& a, u64& b, unsigned addr) {
    asm volatile("ld.shared.v2.u64 {%0, %1}, [%2];" : "=l"(a), "=l"(b) : "r"(addr));
}
__device__ __forceinline__ float2 unpack2(u64 v) {
    float2 f; asm("mov.b64 {%0, %1}, %2;" : "=f"(f.x), "=f"(f.y) : "l"(v)); return f;
}

// =====================================================================================
// Kernel 1: fused MLP.  Block = 64 rows of [B*T], 256 threads.
//   x = relu(LN(relu(LN(LN(ud) @ W1 + b1)) ++ action @ W2 + b2))   (LNs per row)
// smem: W buffer is REUSED (W1 during GEMM1, then W2 loaded into it) -> 94.7 KB -> 2 CTA/SM
// =====================================================================================
__global__ __launch_bounds__(256)
void mlp_kernel(const float* __restrict__ ud, const float* __restrict__ act,
                const float* __restrict__ ln0g, const float* __restrict__ ln0b,
                const float* __restrict__ W1, const float* __restrict__ b1,
                const float* __restrict__ ln1g, const float* __restrict__ ln1b,
                const float* __restrict__ W2, const float* __restrict__ b2,
                const float* __restrict__ ln2g, const float* __restrict__ ln2b)
{
    float* sW  = smem;                 // 128*64 = 8192 floats (holds W1, then W2)
    float* sX  = sW + 128 * 64;        // 64 rows * 132 (pad)  = 8448
    float* sX2 = sX + 64 * 132;        // 64 rows * 100 (pad)  = 6400
    float* sP  = sX2 + 64 * 100;       // params: 640 floats
    // sP: [0:128) ln0g, [128:256) ln0b, [256:320) b1, [320:384) ln1g,
    //     [384:448) ln1b, [448:512) b2, [512:576) ln2g, [576:640) ln2b

    const unsigned sW_a  = (unsigned)__cvta_generic_to_shared(sW);

    const int tid = threadIdx.x;
    for (int i = tid; i < 128 * 64; i += 256) sW[i] = W1[i];
    if (tid < 128) { sP[tid] = ln0g[tid]; sP[128 + tid] = ln0b[tid]; }
    if (tid < 64) {
        sP[256 + tid] = b1[tid];  sP[320 + tid] = ln1g[tid]; sP[384 + tid] = ln1b[tid];
        sP[448 + tid] = b2[tid];  sP[512 + tid] = ln2g[tid]; sP[576 + tid] = ln2b[tid];
    }

    const int r0 = blockIdx.x * 64;

    // load ud tile (64 x 128) into sX, coalesced float4
    #pragma unroll
    for (int j = 0; j < 8; j++) {
        int f = tid + j * 256;              // 2048 float4s
        int row = f >> 5, c4 = f & 31;
        float4 v = reinterpret_cast<const float4*>(ud + (size_t)(r0 + row) * 128)[c4];
        *reinterpret_cast<float4*>(&sX[row * 132 + c4 * 4]) = v;
    }
    // load action tile (64 x 32) into sX2 cols [64,96)
    #pragma unroll
    for (int j = 0; j < 2; j++) {
        int f = tid + j * 256;              // 512 float4s
        int row = f >> 3, c4 = f & 7;
        float4 v = reinterpret_cast<const float4*>(act + (size_t)(r0 + row) * 32)[c4];
        *reinterpret_cast<float4*>(&sX2[row * 100 + 64 + c4 * 4]) = v;
    }
    __syncthreads();

    const int w = tid >> 5, lane = tid & 31;

    // LN0 over 128 features (warp per row, 8 rows/warp)
    for (int rr = 0; rr < 8; rr++) {
        int row = w * 8 + rr;
        float v0 = sX[row * 132 + lane];
        float v1 = sX[row * 132 + lane + 32];
        float v2 = sX[row * 132 + lane + 64];
        float v3 = sX[row * 132 + lane + 96];
        float s = v0 + v1 + v2 + v3;
        float q = v0 * v0 + v1 * v1 + v2 * v2 + v3 * v3;
        #pragma unroll
        for (int o = 16; o; o >>= 1) { s += __shfl_xor_sync(~0u, s, o); q += __shfl_xor_sync(~0u, q, o); }
        float m = s * (1.f / 128.f);
        float var = q * (1.f / 128.f) - m * m;
        float rs = rsqrtf(var + EPSf);
        sX[row * 132 + lane]      = (v0 - m) * rs * sP[lane]      + sP[128 + lane];
        sX[row * 132 + lane + 32] = (v1 - m) * rs * sP[lane + 32] + sP[128 + lane + 32];
        sX[row * 132 + lane + 64] = (v2 - m) * rs * sP[lane + 64] + sP[128 + lane + 64];
        sX[row * 132 + lane + 96] = (v3 - m) * rs * sP[lane + 96] + sP[128 + lane + 96];
    }
    __syncthreads();

    const int ty = tid >> 4, tx = tid & 15;
    const int ry = ty * 4, cx = tx * 4;

    // GEMM1: (64x128)@(128x64), 4x4 micro-tile, packed f32x2
    u64 acc[4][2];
    #pragma unroll
    for (int i = 0; i < 4; i++) { acc[i][0] = 0ull; acc[i][1] = 0ull; }

    #pragma unroll 4
    for (int k = 0; k < 128; k++) {
        u64 w0, w1;
        lds_v2u64(w0, w1, sW_a + (unsigned)(k * 64 + cx) * 4u);
        #pragma unroll
        for (int i = 0; i < 4; i++) {
            u64 a2 = splat2(sX[(ry + i) * 132 + k]);
            ffma2(acc[i][0], a2, w0);
            ffma2(acc[i][1], a2, w1);
        }
    }
    __syncthreads();   // all sX + sW(W1) reads done before overwrite

    // load W2 (96x64) into the W buffer (overlaps LN1 compute)
    for (int i = tid; i < 96 * 64; i += 256) sW[i] = W2[i];

    // y1 = acc + b1 -> sX (reuse, stride 132)
    #pragma unroll
    for (int i = 0; i < 4; i++) {
        float2 p0 = unpack2(acc[i][0]);
        float2 p1 = unpack2(acc[i][1]);
        float4 o;
        o.x = p0.x + sP[256 + cx + 0];
        o.y = p0.y + sP[256 + cx + 1];
        o.z = p1.x + sP[256 + cx + 2];
        o.w = p1.y + sP[256 + cx + 3];
        *reinterpret_cast<float4*>(&sX[(ry + i) * 132 + cx]) = o;
    }
    __syncthreads();

    // LN1 + relu -> sX2 cols [0,64)
    for (int rr = 0; rr < 8; rr++) {
        int row = w * 8 + rr;
        float v0 = sX[row * 132 + lane];
        float v1 = sX[row * 132 + lane + 32];
        float s = v0 + v1, q = v0 * v0 + v1 * v1;
        #pragma unroll
        for (int o = 16; o; o >>= 1) { s += __shfl_xor_sync(~0u, s, o); q += __shfl_xor_sync(~0u, q, o); }
        float m = s * (1.f / 64.f);
        float var = q * (1.f / 64.f) - m * m;
        float rs = rsqrtf(var + EPSf);
        float y0 = (v0 - m) * rs * sP[320 + lane]      + sP[384 + lane];
        float y1 = (v1 - m) * rs * sP[320 + lane + 32] + sP[384 + lane + 32];
        sX2[row * 100 + lane]      = fmaxf(y0, 0.f);
        sX2[row * 100 + lane + 32] = fmaxf(y1, 0.f);
    }
    __syncthreads();   // W2 visible + sX2 ready

    // GEMM2: (64x96)@(96x64), packed f32x2
    u64 acc2[4][2];
    #pragma unroll
    for (int i = 0; i < 4; i++) { acc2[i][0] = 0ull; acc2[i][1] = 0ull; }

    #pragma unroll 4
    for (int k = 0; k < 96; k++) {
        u64 w0, w1;
        lds_v2u64(w0, w1, sW_a + (unsigned)(k * 64 + cx) * 4u);
        #pragma unroll
        for (int i = 0; i < 4; i++) {
            u64 a2 = splat2(sX2[(ry + i) * 100 + k]);
            ffma2(acc2[i][0], a2, w0);
            ffma2(acc2[i][1], a2, w1);
        }
    }
    __syncthreads();

    // y2 = acc2 + b2 -> sX
    #pragma unroll
    for (int i = 0; i < 4; i++) {
        float2 p0 = unpack2(acc2[i][0]);
        float2 p1 = unpack2(acc2[i][1]);
        float4 o;
        o.x = p0.x + sP[448 + cx + 0];
        o.y = p0.y + sP[448 + cx + 1];
        o.z = p1.x + sP[448 + cx + 2];
        o.w = p1.y + sP[448 + cx + 3];
        *reinterpret_cast<float4*>(&sX[(ry + i) * 132 + cx]) = o;
    }
    __syncthreads();

    // LN2 + relu -> global g_x
    for (int rr = 0; rr < 8; rr++) {
        int row = w * 8 + rr;
        float v0 = sX[row * 132 + lane];
        float v1 = sX[row * 132 + lane + 32];
        float s = v0 + v1, q = v0 * v0 + v1 * v1;
        #pragma unroll
        for (int o = 16; o; o >>= 1) { s += __shfl_xor_sync(~0u, s, o); q += __shfl_xor_sync(~0u, q, o); }
        float m = s * (1.f / 64.f);
        float var = q * (1.f / 64.f) - m * m;
        float rs = rsqrtf(var + EPSf);
        float y0 = (v0 - m) * rs * sP[512 + lane]      + sP[576 + lane];
        float y1 = (v1 - m) * rs * sP[512 + lane + 32] + sP[576 + lane + 32];
        size_t base = (size_t)(r0 + row) * 64;
        g_x[base + lane]      = fmaxf(y0, 0.f);
        g_x[base + lane + 32] = fmaxf(y1, 0.f);
    }
}

// =====================================================================================
// Kernel 2: one LSTM time step, both directions (blockIdx.y).
// Block = 64 batch rows, 256 threads. gates = [x_sel, h] @ K + b, fused gate epilogue.
// Thread owns 4 rows x (4 gates x 4 hidden). GEMM uses packed f32x2 FMAs.
// =====================================================================================
__global__ __launch_bounds__(256, 2)
void lstm_step_kernel(const float* __restrict__ fw_k, const float* __restrict__ fw_b,
                      const float* __restrict__ bw_k, const float* __restrict__ bw_b,
                      const int* __restrict__ au, int t, int first)
{
    float* sK  = smem;                  // 64*256 = 16384
    float* sA  = sK + 64 * 256;         // 64*68  = 4352
    float* sB  = sA + 64 * 68;          // 256
    int*   sTs = (int*)(sB + 256);      // 64 (source time per row)
    int*   sAu = sTs + 64;              // 64

    const unsigned sK_a = (unsigned)__cvta_generic_to_shared(sK);

    const int dir = blockIdx.y;
    const float* K    = dir ? bw_k : fw_k;
    const float* bias = dir ? bw_b : fw_b;
    float* gh = g_h[dir];
    float* gc = g_c[dir];
    float* gy = g_ys[dir];

    const int b0 = blockIdx.x * 64;
    const int tid = threadIdx.x;

    sB[tid] = bias[tid];
    if (tid < 64) {
        int b = b0 + tid;
        int a = au[b];
        sAu[tid] = a;
        sTs[tid] = dir ? ((t < a) ? (a - 1 - t) : t) : t;
    }
    __syncthreads();

    const int ty = tid >> 4, tx = tid & 15;
    const int ry = ty * 4, hx = tx * 4;

    u64 acc[4][4][2];   // [row][gate][pair] packed f32x2 accumulators
    #pragma unroll
    for (int i = 0; i < 4; i++)
        #pragma unroll
        for (int g = 0; g < 4; g++) { acc[i][g][0] = 0ull; acc[i][g][1] = 0ull; }

    const int nkc = first ? 1 : 2;   // h==0 on step 0: skip recurrent half
    for (int kc = 0; kc < nkc; kc++) {
        // --- load A chunk (64 rows x 64 cols) ---
        {
            int r = tid >> 2, q = tid & 3;
            int b = b0 + r;
            float4 v0, v1, v2, v3;
            if (kc == 0) {
                const float4* src = reinterpret_cast<const float4*>(g_x + ((size_t)b * 5 + sTs[r]) * 64);
                v0 = src[q * 4 + 0]; v1 = src[q * 4 + 1]; v2 = src[q * 4 + 2]; v3 = src[q * 4 + 3];
            } else {
                const float4* src = reinterpret_cast<const float4*>(gh + (size_t)b * 64);
                v0 = src[q * 4 + 0]; v1 = src[q * 4 + 1]; v2 = src[q * 4 + 2]; v3 = src[q * 4 + 3];
            }
            float4* dst = reinterpret_cast<float4*>(&sA[r * 68 + q * 16]);
            dst[0] = v0; dst[1] = v1; dst[2] = v2; dst[3] = v3;
        }
        // --- load K chunk (64 x 256) ---
        #pragma unroll
        for (int j = 0; j < 16; j++) {
            int f = tid + j * 256;          // 4096 float4s
            int kk = f >> 6, c4 = f & 63;
            reinterpret_cast<float4*>(&sK[kk * 256 + c4 * 4])[0] =
                reinterpret_cast<const float4*>(K + (size_t)(kc * 64 + kk) * 256)[c4];
        }
        __syncthreads();

        #pragma unroll 2
        for (int kk = 0; kk < 64; kk++) {
            u64 av2[4];
            #pragma unroll
            for (int i = 0; i < 4; i++) av2[i] = splat2(sA[(ry + i) * 68 + kk]);
            #pragma unroll
            for (int g = 0; g < 4; g++) {
                u64 w0, w1;
                lds_v2u64(w0, w1, sK_a + (unsigned)(kk * 256 + g * 64 + hx) * 4u);
                #pragma unroll
                for (int i = 0; i < 4; i++) {
                    ffma2(acc[i][g][0], av2[i], w0);
                    ffma2(acc[i][g][1], av2[i], w1);
                }
            }
        }
        __syncthreads();
    }

    // --- gate epilogue (register resident) ---
    float bi[4], bj[4], bf[4], bo[4];
    #pragma unroll
    for (int j = 0; j < 4; j++) {
        bi[j] = sB[0   + hx + j];
        bj[j] = sB[64  + hx + j];
        bf[j] = sB[128 + hx + j];
        bo[j] = sB[192 + hx + j];
    }
    #pragma unroll
    for (int i = 0; i < 4; i++) {
        int b = b0 + ry + i;
        int a = sAu[ry + i];
        bool valid = (t < a);
        size_t hbase = (size_t)b * 64 + hx;
        float4 cprev = make_float4(0.f, 0.f, 0.f, 0.f);
        float4 hprev = make_float4(0.f, 0.f, 0.f, 0.f);
        if (!first) {
            cprev = *reinterpret_cast<const float4*>(gc + hbase);
            hprev = *reinterpret_cast<const float4*>(gh + hbase);
        }
        float ga[4][4];   // [gate][j]
        #pragma unroll
        for (int g = 0; g < 4; g++) {
            float2 p0 = unpack2(acc[i][g][0]);
            float2 p1 = unpack2(acc[i][g][1]);
            ga[g][0] = p0.x; ga[g][1] = p0.y; ga[g][2] = p1.x; ga[g][3] = p1.y;
        }
        float4 cn, hn, yn;
        float* cp = &cprev.x; float* hp = &hprev.x;
        float* cw = &cn.x;    float* hw = &hn.x;    float* yw = &yn.x;
        #pragma unroll
        for (int j = 0; j < 4; j++) {
            float gi = ga[0][j] + bi[j];
            float gj = ga[1][j] + bj[j];
            float gf = ga[2][j] + bf[j];
            float go = ga[3][j] + bo[j];
            float c_ = sigf(gf + 1.f) * cp[j] + sigf(gi) * tanhf(gj);
            float h_ = sigf(go) * tanhf(c_);
            cw[j] = valid ? c_ : cp[j];
            hw[j] = valid ? h_ : hp[j];
            yw[j] = valid ? h_ : 0.f;
        }
        *reinterpret_cast<float4*>(gc + hbase) = cn;
        *reinterpret_cast<float4*>(gh + hbase) = hn;
        *reinterpret_cast<float4*>(gy + ((size_t)b * 5 + t) * 64 + hx) = yn;
    }
}

// =====================================================================================
// Kernel 3: LN over (T,2H) per batch + relu + conv dot + masked sum.  Warp per batch.
// =====================================================================================
__global__ __launch_bounds__(256)
void final_kernel(const float* __restrict__ mask,
                  const float* __restrict__ ln3g, const float* __restrict__ ln3b,
                  const float* __restrict__ convw, const float* __restrict__ convb,
                  const int* __restrict__ au, float* __restrict__ out)
{
    int b = blockIdx.x * 8 + (threadIdx.x >> 5);
    int lane = threadIdx.x & 31;
    int a = au[b];

    float vals[20];   // [t][4]: fw(lane), fw(lane+32), bw(lane), bw(lane+32)
    float s = 0.f, q = 0.f;
    #pragma unroll
    for (int t = 0; t < 5; t++) {
        int rt = (t < a) ? (a - 1 - t) : t;
        size_t fbase = ((size_t)b * 5 + t)  * 64;
        size_t bbase = ((size_t)b * 5 + rt) * 64;
        float v0 = g_ys[0][fbase + lane];
        float v1 = g_ys[0][fbase + lane + 32];
        float v2 = g_ys[1][bbase + lane];
        float v3 = g_ys[1][bbase + lane + 32];
        vals[t * 4 + 0] = v0; vals[t * 4 + 1] = v1;
        vals[t * 4 + 2] = v2; vals[t * 4 + 3] = v3;
        s += v0 + v1 + v2 + v3;
        q += v0 * v0 + v1 * v1 + v2 * v2 + v3 * v3;
    }
    #pragma unroll
    for (int o = 16; o; o >>= 1) { s += __shfl_xor_sync(~0u, s, o); q += __shfl_xor_sync(~0u, q, o); }
    float m = s * (1.f / 640.f);
    float var = q * (1.f / 640.f) - m * m;
    float rs = rsqrtf(var + EPSf);

    // channels: fw -> [lane, lane+32], bw -> [64+lane, 96+lane]
    float g0 = ln3g[lane],      c0 = ln3b[lane],      w0 = convw[lane];
    float g1 = ln3g[lane + 32], c1 = ln3b[lane + 32], w1 = convw[lane + 32];
    float g2 = ln3g[lane + 64], c2 = ln3b[lane + 64], w2 = convw[lane + 64];
    float g3 = ln3g[lane + 96], c3 = ln3b[lane + 96], w3 = convw[lane + 96];

    float accq = 0.f, msum = 0.f;
    #pragma unroll
    for (int t = 0; t < 5; t++) {
        float p =
            fmaxf((vals[t*4+0] - m) * rs * g0 + c0, 0.f) * w0 +
            fmaxf((vals[t*4+1] - m) * rs * g1 + c1, 0.f) * w1 +
            fmaxf((vals[t*4+2] - m) * rs * g2 + c2, 0.f) * w2 +
            fmaxf((vals[t*4+3] - m) * rs * g3 + c3, 0.f) * w3;
        float mk = mask[(size_t)b * 5 + t];
        accq += p * mk;
        msum += mk;
    }
    #pragma unroll
    for (int o = 16; o; o >>= 1) accq += __shfl_xor_sync(~0u, accq, o);
    if (lane == 0) out[b] = accq + convb[0] * msum;
}

// =====================================================================================
extern "C" void kernel_launch(void* const* d_in, const int* in_sizes, int n_in,
                              void* d_out, int out_size)
{
    (void)in_sizes; (void)n_in; (void)out_size;
    const float* ud     = (const float*)d_in[0];
    const float* action = (const float*)d_in[1];
    const float* mask   = (const float*)d_in[2];
    const float* ln0g   = (const float*)d_in[3];
    const float* ln0b   = (const float*)d_in[4];
    const float* W1     = (const float*)d_in[5];
    const float* b1     = (const float*)d_in[6];
    const float* ln1g   = (const float*)d_in[7];
    const float* ln1b   = (const float*)d_in[8];
    const float* W2     = (const float*)d_in[9];
    const float* b2     = (const float*)d_in[10];
    const float* ln2g   = (const float*)d_in[11];
    const float* ln2b   = (const float*)d_in[12];
    const float* fw_k   = (const float*)d_in[13];
    const float* fw_b   = (const float*)d_in[14];
    const float* bw_k   = (const float*)d_in[15];
    const float* bw_b   = (const float*)d_in[16];
    const float* ln3g   = (const float*)d_in[17];
    const float* ln3b   = (const float*)d_in[18];
    const float* convw  = (const float*)d_in[19];
    const float* convb  = (const float*)d_in[20];
    const int*   au     = (const int*)d_in[21];

    const int MLP_SMEM  = (128*64 + 64*132 + 64*100 + 640) * 4;          // 94720 B
    const int LSTM_SMEM = (64*256 + 64*68 + 256 + 64 + 64) * 4;          // 84480 B

    cudaFuncSetAttribute(mlp_kernel,       cudaFuncAttributeMaxDynamicSharedMemorySize, MLP_SMEM);
    cudaFuncSetAttribute(lstm_step_kernel, cudaFuncAttributeMaxDynamicSharedMemorySize, LSTM_SMEM);

    mlp_kernel<<<BT / 64, 256, MLP_SMEM>>>(ud, action, ln0g, ln0b, W1, b1,
                                           ln1g, ln1b, W2, b2, ln2g, ln2b);

    for (int t = 0; t < Tn; t++) {
        lstm_step_kernel<<<dim3(Bn / 64, 2), 256, LSTM_SMEM>>>(
            fw_k, fw_b, bw_k, bw_b, au, t, (t == 0) ? 1 : 0);
    }

    final_kernel<<<Bn / 8, 256>>>(mask, ln3g, ln3b, convw, convb, au, (float*)d_out);
}

// round 4
// speedup vs baseline: 1.2686x; 1.1111x over previous
#include <cuda_runtime.h>
#include <math.h>

#define Bn   65536
#define Tn   5
#define OBSn 128
#define ACTn 32
#define Hn   64
#define BT   (Bn*Tn)
#define EPSf 1e-12f

typedef unsigned long long u64;

// ---------------- scratch (device globals; no allocation allowed) ----------------
__device__ float g_x[BT * Hn];          // MLP output, [B*T, 64]
__device__ float g_ys[2][BT * Hn];      // LSTM outputs per direction (bw in reversed-time order)

extern __shared__ float smem[];

// ---------------- packed f32x2 helpers (FFMA2 — ptxas never emits this itself) ----
__device__ __forceinline__ u64 splat2(float x) {
    u64 r; asm("mov.b64 %0, {%1, %1};" : "=l"(r) : "f"(x)); return r;
}
__device__ __forceinline__ void ffma2(u64& d, u64 a, u64 b) {
    asm("fma.rn.f32x2 %0, %1, %2, %0;" : "+l"(d) : "l"(a), "l"(b));
}
__device__ __forceinline__ void lds_v2u64(u64& a, u64& b, unsigned addr) {
    asm volatile("ld.shared.v2.u64 {%0, %1}, [%2];" : "=l"(a), "=l"(b) : "r"(addr));
}
__device__ __forceinline__ float2 unpack2(u64 v) {
    float2 f; asm("mov.b64 {%0, %1}, %2;" : "=f"(f.x), "=f"(f.y) : "l"(v)); return f;
}

// fast, accurate-enough (~1e-6) gate nonlinearities
__device__ __forceinline__ float sig_f(float x) {
    return __fdividef(1.f, 1.f + __expf(-x));
}
__device__ __forceinline__ float tanh_f(float x) {
    return __fdividef(2.f, 1.f + __expf(-2.f * x)) - 1.f;
}

#define CP16(dst, src) asm volatile("cp.async.ca.shared.global [%0], [%1], 16;" :: "r"(dst), "l"(src))
#define CP_COMMIT()    asm volatile("cp.async.commit_group;")

// =====================================================================================
// Kernel 1: fused MLP (unchanged from R3).  Block = 64 rows of [B*T], 256 threads.
// =====================================================================================
__global__ __launch_bounds__(256)
void mlp_kernel(const float* __restrict__ ud, const float* __restrict__ act,
                const float* __restrict__ ln0g, const float* __restrict__ ln0b,
                const float* __restrict__ W1, const float* __restrict__ b1,
                const float* __restrict__ ln1g, const float* __restrict__ ln1b,
                const float* __restrict__ W2, const float* __restrict__ b2,
                const float* __restrict__ ln2g, const float* __restrict__ ln2b)
{
    float* sW  = smem;                 // 128*64 floats (holds W1, then W2)
    float* sX  = sW + 128 * 64;        // 64 * 132
    float* sX2 = sX + 64 * 132;        // 64 * 100
    float* sP  = sX2 + 64 * 100;       // 640

    const unsigned sW_a  = (unsigned)__cvta_generic_to_shared(sW);

    const int tid = threadIdx.x;
    for (int i = tid; i < 128 * 64; i += 256) sW[i] = W1[i];
    if (tid < 128) { sP[tid] = ln0g[tid]; sP[128 + tid] = ln0b[tid]; }
    if (tid < 64) {
        sP[256 + tid] = b1[tid];  sP[320 + tid] = ln1g[tid]; sP[384 + tid] = ln1b[tid];
        sP[448 + tid] = b2[tid];  sP[512 + tid] = ln2g[tid]; sP[576 + tid] = ln2b[tid];
    }

    const int r0 = blockIdx.x * 64;

    #pragma unroll
    for (int j = 0; j < 8; j++) {
        int f = tid + j * 256;
        int row = f >> 5, c4 = f & 31;
        float4 v = reinterpret_cast<const float4*>(ud + (size_t)(r0 + row) * 128)[c4];
        *reinterpret_cast<float4*>(&sX[row * 132 + c4 * 4]) = v;
    }
    #pragma unroll
    for (int j = 0; j < 2; j++) {
        int f = tid + j * 256;
        int row = f >> 3, c4 = f & 7;
        float4 v = reinterpret_cast<const float4*>(act + (size_t)(r0 + row) * 32)[c4];
        *reinterpret_cast<float4*>(&sX2[row * 100 + 64 + c4 * 4]) = v;
    }
    __syncthreads();

    const int w = tid >> 5, lane = tid & 31;

    for (int rr = 0; rr < 8; rr++) {
        int row = w * 8 + rr;
        float v0 = sX[row * 132 + lane];
        float v1 = sX[row * 132 + lane + 32];
        float v2 = sX[row * 132 + lane + 64];
        float v3 = sX[row * 132 + lane + 96];
        float s = v0 + v1 + v2 + v3;
        float q = v0 * v0 + v1 * v1 + v2 * v2 + v3 * v3;
        #pragma unroll
        for (int o = 16; o; o >>= 1) { s += __shfl_xor_sync(~0u, s, o); q += __shfl_xor_sync(~0u, q, o); }
        float m = s * (1.f / 128.f);
        float var = q * (1.f / 128.f) - m * m;
        float rs = rsqrtf(var + EPSf);
        sX[row * 132 + lane]      = (v0 - m) * rs * sP[lane]      + sP[128 + lane];
        sX[row * 132 + lane + 32] = (v1 - m) * rs * sP[lane + 32] + sP[128 + lane + 32];
        sX[row * 132 + lane + 64] = (v2 - m) * rs * sP[lane + 64] + sP[128 + lane + 64];
        sX[row * 132 + lane + 96] = (v3 - m) * rs * sP[lane + 96] + sP[128 + lane + 96];
    }
    __syncthreads();

    const int ty = tid >> 4, tx = tid & 15;
    const int ry = ty * 4, cx = tx * 4;

    u64 acc[4][2];
    #pragma unroll
    for (int i = 0; i < 4; i++) { acc[i][0] = 0ull; acc[i][1] = 0ull; }

    #pragma unroll 4
    for (int k = 0; k < 128; k++) {
        u64 w0, w1;
        lds_v2u64(w0, w1, sW_a + (unsigned)(k * 64 + cx) * 4u);
        #pragma unroll
        for (int i = 0; i < 4; i++) {
            u64 a2 = splat2(sX[(ry + i) * 132 + k]);
            ffma2(acc[i][0], a2, w0);
            ffma2(acc[i][1], a2, w1);
        }
    }
    __syncthreads();

    for (int i = tid; i < 96 * 64; i += 256) sW[i] = W2[i];

    #pragma unroll
    for (int i = 0; i < 4; i++) {
        float2 p0 = unpack2(acc[i][0]);
        float2 p1 = unpack2(acc[i][1]);
        float4 o;
        o.x = p0.x + sP[256 + cx + 0];
        o.y = p0.y + sP[256 + cx + 1];
        o.z = p1.x + sP[256 + cx + 2];
        o.w = p1.y + sP[256 + cx + 3];
        *reinterpret_cast<float4*>(&sX[(ry + i) * 132 + cx]) = o;
    }
    __syncthreads();

    for (int rr = 0; rr < 8; rr++) {
        int row = w * 8 + rr;
        float v0 = sX[row * 132 + lane];
        float v1 = sX[row * 132 + lane + 32];
        float s = v0 + v1, q = v0 * v0 + v1 * v1;
        #pragma unroll
        for (int o = 16; o; o >>= 1) { s += __shfl_xor_sync(~0u, s, o); q += __shfl_xor_sync(~0u, q, o); }
        float m = s * (1.f / 64.f);
        float var = q * (1.f / 64.f) - m * m;
        float rs = rsqrtf(var + EPSf);
        float y0 = (v0 - m) * rs * sP[320 + lane]      + sP[384 + lane];
        float y1 = (v1 - m) * rs * sP[320 + lane + 32] + sP[384 + lane + 32];
        sX2[row * 100 + lane]      = fmaxf(y0, 0.f);
        sX2[row * 100 + lane + 32] = fmaxf(y1, 0.f);
    }
    __syncthreads();

    u64 acc2[4][2];
    #pragma unroll
    for (int i = 0; i < 4; i++) { acc2[i][0] = 0ull; acc2[i][1] = 0ull; }

    #pragma unroll 4
    for (int k = 0; k < 96; k++) {
        u64 w0, w1;
        lds_v2u64(w0, w1, sW_a + (unsigned)(k * 64 + cx) * 4u);
        #pragma unroll
        for (int i = 0; i < 4; i++) {
            u64 a2 = splat2(sX2[(ry + i) * 100 + k]);
            ffma2(acc2[i][0], a2, w0);
            ffma2(acc2[i][1], a2, w1);
        }
    }
    __syncthreads();

    #pragma unroll
    for (int i = 0; i < 4; i++) {
        float2 p0 = unpack2(acc2[i][0]);
        float2 p1 = unpack2(acc2[i][1]);
        float4 o;
        o.x = p0.x + sP[448 + cx + 0];
        o.y = p0.y + sP[448 + cx + 1];
        o.z = p1.x + sP[448 + cx + 2];
        o.w = p1.y + sP[448 + cx + 3];
        *reinterpret_cast<float4*>(&sX[(ry + i) * 132 + cx]) = o;
    }
    __syncthreads();

    for (int rr = 0; rr < 8; rr++) {
        int row = w * 8 + rr;
        float v0 = sX[row * 132 + lane];
        float v1 = sX[row * 132 + lane + 32];
        float s = v0 + v1, q = v0 * v0 + v1 * v1;
        #pragma unroll
        for (int o = 16; o; o >>= 1) { s += __shfl_xor_sync(~0u, s, o); q += __shfl_xor_sync(~0u, q, o); }
        float m = s * (1.f / 64.f);
        float var = q * (1.f / 64.f) - m * m;
        float rs = rsqrtf(var + EPSf);
        float y0 = (v0 - m) * rs * sP[512 + lane]      + sP[576 + lane];
        float y1 = (v1 - m) * rs * sP[512 + lane + 32] + sP[576 + lane + 32];
        size_t base = (size_t)(r0 + row) * 64;
        g_x[base + lane]      = fmaxf(y0, 0.f);
        g_x[base + lane + 32] = fmaxf(y1, 0.f);
    }
}

// =====================================================================================
// Kernel 2: persistent bidirectional LSTM.
//   grid = (512, 2): 128 batch rows per CTA, blockIdx.y = direction.
//   512 threads. Thread tile = 8 rows x (4 gates x 2 hcols). c in regs; h via smem.
//   K resident in smem (permuted so per-thread weights are contiguous); x double-
//   buffered via cp.async; all 5 timesteps in one kernel.
// smem layout (floats):
//   sKp   [0, 32768)        permuted kernel: sKp[k*256 + (hc>>1)*8 + g*2 + (hc&1)]
//   xbuf  [32768, 49152)    2 x 128 x 64
//   sH    [49152, 57600)    128 x 66 (padded)
//   sAu   [57600, 57728)    au per row (int)
// =====================================================================================
__global__ __launch_bounds__(512, 1)
void lstm_persistent_kernel(const float* __restrict__ fw_k, const float* __restrict__ fw_b,
                            const float* __restrict__ bw_k, const float* __restrict__ bw_b,
                            const int* __restrict__ au)
{
    float* sKp  = smem;
    float* xbuf = smem + 32768;
    float* sH   = smem + 49152;
    int*   sAu  = (int*)(smem + 57600);

    const unsigned sKp_a = (unsigned)__cvta_generic_to_shared(sKp);

    const int dir = blockIdx.y;
    const float* K    = dir ? bw_k : fw_k;
    const float* bias = dir ? bw_b : fw_b;
    float* gy = g_ys[dir];

    const int b0  = blockIdx.x * 128;
    const int tid = threadIdx.x;
    const int tx  = tid & 31;        // hcol pair index: hx = tx*2
    const int ty  = tid >> 5;        // row group: rows ty*8 .. ty*8+7
    const int hx  = tx * 2;
    const int r0  = ty * 8;

    // ---- prefetch x_0 and x_1 (cp.async), reading au from global for bw index ----
    {
        int row = tid >> 2, seg = tid & 3;
        int b = b0 + row;
        int a = au[b];
        #pragma unroll
        for (int tt = 0; tt < 2; tt++) {
            int ts = dir ? ((tt < a) ? (a - 1 - tt) : tt) : tt;
            const float* src = g_x + ((size_t)b * 5 + ts) * 64 + seg * 16;
            unsigned dst = (unsigned)__cvta_generic_to_shared(xbuf + (tt & 1) * 8192 + row * 64 + seg * 16);
            #pragma unroll
            for (int q = 0; q < 4; q++) CP16(dst + q * 16, src + q * 4);
            CP_COMMIT();
        }
        if (seg == 0) sAu[row] = a;
    }

    // ---- load + permute K into smem: target idx = k*256 + (hc>>1)*8 + g*2 + (hc&1) ----
    #pragma unroll
    for (int it = 0; it < 16; it++) {
        int f = tid + it * 512;              // 8192 float4s
        int kk = f >> 6, c4 = f & 63;
        float4 v = reinterpret_cast<const float4*>(K + (size_t)kk * 256)[c4];
        int g  = c4 >> 4;
        int p0 = (c4 & 15) * 2;
        float2* d0 = reinterpret_cast<float2*>(&sKp[kk * 256 + p0 * 8 + g * 2]);
        float2* d1 = reinterpret_cast<float2*>(&sKp[kk * 256 + (p0 + 1) * 8 + g * 2]);
        *d0 = make_float2(v.x, v.y);
        *d1 = make_float2(v.z, v.w);
    }

    // ---- biases for this thread's 4 gates x 2 hcols ----
    float2 bg[4];
    #pragma unroll
    for (int g = 0; g < 4; g++)
        bg[g] = *reinterpret_cast<const float2*>(bias + g * 64 + hx);

    // ---- per-thread persistent cell state ----
    float2 cc[8];
    #pragma unroll
    for (int i = 0; i < 8; i++) cc[i] = make_float2(0.f, 0.f);

    for (int t = 0; t < 5; t++) {
        // x_t must have landed; (h STS from prev step + cp.async) made visible
        if (t < 4) { asm volatile("cp.async.wait_group 1;" ::: "memory"); }
        else       { asm volatile("cp.async.wait_group 0;" ::: "memory"); }
        __syncthreads();

        const float* xb = xbuf + (t & 1) * 8192;

        u64 acc[8][4];
        #pragma unroll
        for (int i = 0; i < 8; i++)
            #pragma unroll
            for (int g = 0; g < 4; g++) acc[i][g] = 0ull;

        // ---- GEMM, x half (k = 0..63) ----
        #pragma unroll 2
        for (int k = 0; k < 64; k += 2) {
            u64 wa0, wa1, wb0, wb1;
            lds_v2u64(wa0, wa1, sKp_a + (unsigned)(k * 256 + tx * 8) * 4u);
            lds_v2u64(wb0, wb1, sKp_a + (unsigned)((k + 1) * 256 + tx * 8) * 4u);
            #pragma unroll
            for (int i = 0; i < 8; i++) {
                float2 a = *reinterpret_cast<const float2*>(&xb[(r0 + i) * 64 + k]);
                u64 sx = splat2(a.x), sy = splat2(a.y);
                ffma2(acc[i][0], sx, wa0); ffma2(acc[i][1], sx, wa1);
                u64 wa2, wa3;
                lds_v2u64(wa2, wa3, sKp_a + (unsigned)(k * 256 + tx * 8 + 4) * 4u);
                ffma2(acc[i][2], sx, wa2); ffma2(acc[i][3], sx, wa3);
                ffma2(acc[i][0], sy, wb0); ffma2(acc[i][1], sy, wb1);
                u64 wb2, wb3;
                lds_v2u64(wb2, wb3, sKp_a + (unsigned)((k + 1) * 256 + tx * 8 + 4) * 4u);
                ffma2(acc[i][2], sy, wb2); ffma2(acc[i][3], sy, wb3);
            }
        }

        // ---- GEMM, h half (k = 64..127), skipped on t == 0 (h == 0) ----
        if (t > 0) {
            #pragma unroll 2
            for (int k = 0; k < 64; k += 2) {
                u64 wa0, wa1, wa2, wa3, wb0, wb1, wb2, wb3;
                lds_v2u64(wa0, wa1, sKp_a + (unsigned)((k + 64) * 256 + tx * 8) * 4u);
                lds_v2u64(wa2, wa3, sKp_a + (unsigned)((k + 64) * 256 + tx * 8 + 4) * 4u);
                lds_v2u64(wb0, wb1, sKp_a + (unsigned)((k + 65) * 256 + tx * 8) * 4u);
                lds_v2u64(wb2, wb3, sKp_a + (unsigned)((k + 65) * 256 + tx * 8 + 4) * 4u);
                #pragma unroll
                for (int i = 0; i < 8; i++) {
                    float2 a = *reinterpret_cast<const float2*>(&sH[(r0 + i) * 66 + k]);
                    u64 sx = splat2(a.x), sy = splat2(a.y);
                    ffma2(acc[i][0], sx, wa0); ffma2(acc[i][1], sx, wa1);
                    ffma2(acc[i][2], sx, wa2); ffma2(acc[i][3], sx, wa3);
                    ffma2(acc[i][0], sy, wb0); ffma2(acc[i][1], sy, wb1);
                    ffma2(acc[i][2], sy, wb2); ffma2(acc[i][3], sy, wb3);
                }
            }
        }

        __syncthreads();   // all GEMM reads of sH / xbuf[t&1] complete

        // ---- prefetch x_{t+2} into the buffer just freed ----
        if (t + 2 < 5) {
            int row = tid >> 2, seg = tid & 3;
            int b = b0 + row;
            int tt = t + 2;
            int a = sAu[row];
            int ts = dir ? ((tt < a) ? (a - 1 - tt) : tt) : tt;
            const float* src = g_x + ((size_t)b * 5 + ts) * 64 + seg * 16;
            unsigned dst = (unsigned)__cvta_generic_to_shared(xbuf + (tt & 1) * 8192 + row * 64 + seg * 16);
            #pragma unroll
            for (int q = 0; q < 4; q++) CP16(dst + q * 16, src + q * 4);
            CP_COMMIT();
        }

        // ---- gate epilogue: thread owns (8 rows x 2 hcols) of c, h ----
        #pragma unroll
        for (int i = 0; i < 8; i++) {
            int row = r0 + i;
            int a = sAu[row];
            bool valid = (t < a);
            float2 gi = unpack2(acc[i][0]);
            float2 gj = unpack2(acc[i][1]);
            float2 gf = unpack2(acc[i][2]);
            float2 go = unpack2(acc[i][3]);
            gi.x += bg[0].x; gi.y += bg[0].y;
            gj.x += bg[1].x; gj.y += bg[1].y;
            gf.x += bg[2].x; gf.y += bg[2].y;
            go.x += bg[3].x; go.y += bg[3].y;

            float2 hold = (t > 0) ? *reinterpret_cast<const float2*>(&sH[row * 66 + hx])
                                  : make_float2(0.f, 0.f);
            float2 cold = cc[i];

            float cnx = sig_f(gf.x + 1.f) * cold.x + sig_f(gi.x) * tanh_f(gj.x);
            float cny = sig_f(gf.y + 1.f) * cold.y + sig_f(gi.y) * tanh_f(gj.y);
            float hnx = sig_f(go.x) * tanh_f(cnx);
            float hny = sig_f(go.y) * tanh_f(cny);

            cc[i].x = valid ? cnx : cold.x;
            cc[i].y = valid ? cny : cold.y;
            float2 hw = make_float2(valid ? hnx : hold.x, valid ? hny : hold.y);
            *reinterpret_cast<float2*>(&sH[row * 66 + hx]) = hw;

            float2 yw = make_float2(valid ? hnx : 0.f, valid ? hny : 0.f);
            *reinterpret_cast<float2*>(gy + ((size_t)(b0 + row) * 5 + t) * 64 + hx) = yw;
        }
        // loop-top __syncthreads() publishes sH writes before next GEMM
    }
}

// =====================================================================================
// Kernel 3: LN over (T,2H) per batch + relu + conv dot + masked sum.  Warp per batch.
// =====================================================================================
__global__ __launch_bounds__(256)
void final_kernel(const float* __restrict__ mask,
                  const float* __restrict__ ln3g, const float* __restrict__ ln3b,
                  const float* __restrict__ convw, const float* __restrict__ convb,
                  const int* __restrict__ au, float* __restrict__ out)
{
    int b = blockIdx.x * 8 + (threadIdx.x >> 5);
    int lane = threadIdx.x & 31;
    int a = au[b];

    float vals[20];
    float s = 0.f, q = 0.f;
    #pragma unroll
    for (int t = 0; t < 5; t++) {
        int rt = (t < a) ? (a - 1 - t) : t;
        size_t fbase = ((size_t)b * 5 + t)  * 64;
        size_t bbase = ((size_t)b * 5 + rt) * 64;
        float v0 = g_ys[0][fbase + lane];
        float v1 = g_ys[0][fbase + lane + 32];
        float v2 = g_ys[1][bbase + lane];
        float v3 = g_ys[1][bbase + lane + 32];
        vals[t * 4 + 0] = v0; vals[t * 4 + 1] = v1;
        vals[t * 4 + 2] = v2; vals[t * 4 + 3] = v3;
        s += v0 + v1 + v2 + v3;
        q += v0 * v0 + v1 * v1 + v2 * v2 + v3 * v3;
    }
    #pragma unroll
    for (int o = 16; o; o >>= 1) { s += __shfl_xor_sync(~0u, s, o); q += __shfl_xor_sync(~0u, q, o); }
    float m = s * (1.f / 640.f);
    float var = q * (1.f / 640.f) - m * m;
    float rs = rsqrtf(var + EPSf);

    float g0 = ln3g[lane],      c0 = ln3b[lane],      w0 = convw[lane];
    float g1 = ln3g[lane + 32], c1 = ln3b[lane + 32], w1 = convw[lane + 32];
    float g2 = ln3g[lane + 64], c2 = ln3b[lane + 64], w2 = convw[lane + 64];
    float g3 = ln3g[lane + 96], c3 = ln3b[lane + 96], w3 = convw[lane + 96];

    float accq = 0.f, msum = 0.f;
    #pragma unroll
    for (int t = 0; t < 5; t++) {
        float p =
            fmaxf((vals[t*4+0] - m) * rs * g0 + c0, 0.f) * w0 +
            fmaxf((vals[t*4+1] - m) * rs * g1 + c1, 0.f) * w1 +
            fmaxf((vals[t*4+2] - m) * rs * g2 + c2, 0.f) * w2 +
            fmaxf((vals[t*4+3] - m) * rs * g3 + c3, 0.f) * w3;
        float mk = mask[(size_t)b * 5 + t];
        accq += p * mk;
        msum += mk;
    }
    #pragma unroll
    for (int o = 16; o; o >>= 1) accq += __shfl_xor_sync(~0u, accq, o);
    if (lane == 0) out[b] = accq + convb[0] * msum;
}

// =====================================================================================
extern "C" void kernel_launch(void* const* d_in, const int* in_sizes, int n_in,
                              void* d_out, int out_size)
{
    (void)in_sizes; (void)n_in; (void)out_size;
    const float* ud     = (const float*)d_in[0];
    const float* action = (const float*)d_in[1];
    const float* mask   = (const float*)d_in[2];
    const float* ln0g   = (const float*)d_in[3];
    const float* ln0b   = (const float*)d_in[4];
    const float* W1     = (const float*)d_in[5];
    const float* b1     = (const float*)d_in[6];
    const float* ln1g   = (const float*)d_in[7];
    const float* ln1b   = (const float*)d_in[8];
    const float* W2     = (const float*)d_in[9];
    const float* b2     = (const float*)d_in[10];
    const float* ln2g   = (const float*)d_in[11];
    const float* ln2b   = (const float*)d_in[12];
    const float* fw_k   = (const float*)d_in[13];
    const float* fw_b   = (const float*)d_in[14];
    const float* bw_k   = (const float*)d_in[15];
    const float* bw_b   = (const float*)d_in[16];
    const float* ln3g   = (const float*)d_in[17];
    const float* ln3b   = (const float*)d_in[18];
    const float* convw  = (const float*)d_in[19];
    const float* convb  = (const float*)d_in[20];
    const int*   au     = (const int*)d_in[21];

    const int MLP_SMEM  = (128*64 + 64*132 + 64*100 + 640) * 4;   // 94720 B
    const int LSTM_SMEM = 57728 * 4;                              // 230912 B

    cudaFuncSetAttribute(mlp_kernel,             cudaFuncAttributeMaxDynamicSharedMemorySize, MLP_SMEM);
    cudaFuncSetAttribute(lstm_persistent_kernel, cudaFuncAttributeMaxDynamicSharedMemorySize, LSTM_SMEM);

    mlp_kernel<<<BT / 64, 256, MLP_SMEM>>>(ud, action, ln0g, ln0b, W1, b1,
                                           ln1g, ln1b, W2, b2, ln2g, ln2b);

    lstm_persistent_kernel<<<dim3(Bn / 128, 2), 512, LSTM_SMEM>>>(fw_k, fw_b, bw_k, bw_b, au);

    final_kernel<<<Bn / 8, 256>>>(mask, ln3g, ln3b, convw, convb, au, (float*)d_out);
}